// round 14
// baseline (speedup 1.0000x reference)
#include <cuda_runtime.h>
#include <cuda_fp16.h>
#include <cstdint>

#define HH 16
#define LLEN 512
#define DD 1024
#define BB 4
#define BHN (BB*HH)      // 64
#define MR (BB*LLEN)     // 2048

// ---------------- scratch (no cudaMalloc allowed) ----------------
__device__ __half g_q16[MR * DD];        // fp16 copies of inputs
__device__ __half g_k16[MR * DD];
__device__ __half g_v16[MR * DD];
__device__ __half g_wth[4 * DD * DD];    // fp16 transposed weights [z][n][k]
__device__ __half g_qh[BHN * LLEN * 64]; // [bh][l][dk], pre-scaled by 1/8
__device__ __half g_kh[BHN * LLEN * 64]; // [bh][l][dk]
__device__ __half g_vt[BHN * 64 * LLEN]; // [bh][dv][l]  (transposed V)
__device__ __half g_ctx[MR * DD];        // attention output fp16
__device__ float  g_pre[MR * DD];        // pre-LayerNorm fp32

// ---------------- helpers ----------------
__device__ __forceinline__ void cpa16(unsigned dst, const void* src) {
    asm volatile("cp.async.cg.shared.global [%0], [%1], 16;" :: "r"(dst), "l"(src));
}
#define CP_COMMIT() asm volatile("cp.async.commit_group;")
#define CP_WAIT(N)  asm volatile("cp.async.wait_group %0;" :: "n"(N))

__device__ __forceinline__ unsigned sa32(const void* p) {
    return (unsigned)__cvta_generic_to_shared(p);
}

// fp16 mma m16n8k16, fp32 accumulate
__device__ __forceinline__ void mma16(float (&c)[4], const unsigned (&a)[4],
                                      const unsigned (&b)[2]) {
    asm("mma.sync.aligned.m16n8k16.row.col.f32.f16.f16.f32 "
        "{%0,%1,%2,%3}, {%4,%5,%6,%7}, {%8,%9}, {%0,%1,%2,%3};"
        : "+f"(c[0]), "+f"(c[1]), "+f"(c[2]), "+f"(c[3])
        : "r"(a[0]), "r"(a[1]), "r"(a[2]), "r"(a[3]), "r"(b[0]), "r"(b[1]));
}

__device__ __forceinline__ void ldsm_x4(unsigned& r0, unsigned& r1,
                                        unsigned& r2, unsigned& r3, unsigned addr) {
    asm volatile("ldmatrix.sync.aligned.m8n8.x4.shared.b16 {%0,%1,%2,%3}, [%4];"
                 : "=r"(r0), "=r"(r1), "=r"(r2), "=r"(r3) : "r"(addr));
}
__device__ __forceinline__ void ldsm_x2(unsigned& r0, unsigned& r1, unsigned addr) {
    asm volatile("ldmatrix.sync.aligned.m8n8.x2.shared.b16 {%0,%1}, [%2];"
                 : "=r"(r0), "=r"(r1) : "r"(addr));
}

__device__ __forceinline__ unsigned pack_h2(float a, float b) {
    __half2 h = __floats2half2_rn(a, b);
    return *reinterpret_cast<unsigned*>(&h);
}

// ---------------- prep: weight transpose (z<4) + input convert (z>=4) --------
__global__ __launch_bounds__(256)
void prep_kernel(const float* __restrict__ q, const float* __restrict__ k,
                 const float* __restrict__ v,
                 const float* __restrict__ wq, const float* __restrict__ wk,
                 const float* __restrict__ wv, const float* __restrict__ wo)
{
    __shared__ float t[32][33];
    const int z = blockIdx.z;
    if (z < 4) {
        const float* src = (z == 0) ? wq : (z == 1) ? wk : (z == 2) ? wv : wo;
        __half* dst = g_wth + (size_t)z * DD * DD;
        const int x = blockIdx.x * 32, y = blockIdx.y * 32;  // x: n, y: k
        const int tx = threadIdx.x & 31, ty = threadIdx.x >> 5;
#pragma unroll
        for (int i = 0; i < 4; i++)
            t[ty + 8 * i][tx] = src[(size_t)(y + ty + 8 * i) * DD + x + tx];
        __syncthreads();
#pragma unroll
        for (int i = 0; i < 4; i++)
            dst[(size_t)(x + ty + 8 * i) * DD + y + tx] =
                __float2half(t[tx][ty + 8 * i]);
    } else {
        const float* src = (z == 4) ? q : (z == 5) ? k : v;
        __half* dst = (z == 4) ? g_q16 : (z == 5) ? g_k16 : g_v16;
        const size_t base =
            ((size_t)(blockIdx.y * 32 + blockIdx.x) * 256 + threadIdx.x) * 8;
#pragma unroll
        for (int i = 0; i < 2; i++) {
            float4 a = *(const float4*)&src[base + i * 4];
            *(__half2*)&dst[base + i * 4]     = __floats2half2_rn(a.x, a.y);
            *(__half2*)&dst[base + i * 4 + 2] = __floats2half2_rn(a.z, a.w);
        }
    }
}

// ---------------- FP16 GEMM: C[128x128] tile, K=1024 in 16 chunks of 64 ------
#define GA_STRIDE 72
#define GA_HALF   (128 * GA_STRIDE)          // 9216
#define GEMM_SMEM_BYTES (4 * GA_HALF * 2)    // 73728

__global__ __launch_bounds__(256)
void gemm16(int is_outproj, const float* __restrict__ resid,
            const float* __restrict__ b0p, const float* __restrict__ b1p,
            const float* __restrict__ b2p)
{
    extern __shared__ __half smh[];
    __half* As = smh;
    __half* Bs = smh + 2 * GA_HALF;

    const int tid = threadIdx.x;
    const int w = tid >> 5, lane = tid & 31;
    const int g = lane >> 2, t = lane & 3;
    const int wm = (w & 1) * 64, wn = (w >> 1) * 32;
    const int m0 = blockIdx.y * 128, n0 = blockIdx.x * 128;
    const int z = blockIdx.z;

    const __half* Ap = is_outproj ? g_ctx
                     : (z == 0) ? g_q16 : (z == 1) ? g_k16 : g_v16;
    const __half* Bt = g_wth + (size_t)(is_outproj ? 3 : z) * DD * DD;
    const float* bias = is_outproj ? b0p : (z == 0) ? b0p : (z == 1) ? b1p : b2p;

    // ldmatrix lane offsets (bytes within a buffer)
    const unsigned aoff = (wm + (lane & 15)) * 144 + ((lane >> 4) & 1) * 16;
    const unsigned boff = (wn + (lane & 7)) * 144 + ((lane >> 3) & 1) * 16;

    auto stage = [&](int kt, int buf) {
        const int k0 = kt * 64;
        const unsigned ab = sa32(As + buf * GA_HALF);
        const unsigned bb = sa32(Bs + buf * GA_HALF);
#pragma unroll
        for (int i = 0; i < 4; i++) {
            const int id = i * 256 + tid;
            const int row = id >> 3, c16 = id & 7;
            cpa16(ab + row * 144 + c16 * 16, Ap + (size_t)(m0 + row) * DD + k0 + c16 * 8);
            cpa16(bb + row * 144 + c16 * 16, Bt + (size_t)(n0 + row) * DD + k0 + c16 * 8);
        }
    };

    float acc[4][4][4];
#pragma unroll
    for (int mt = 0; mt < 4; mt++)
#pragma unroll
        for (int nt = 0; nt < 4; nt++)
#pragma unroll
            for (int e = 0; e < 4; e++) acc[mt][nt][e] = 0.f;

    stage(0, 0); CP_COMMIT();

    for (int kt = 0; kt < 16; kt++) {
        if (kt < 15) { stage(kt + 1, (kt + 1) & 1); CP_COMMIT(); CP_WAIT(1); }
        else         { CP_WAIT(0); }
        __syncthreads();

        const unsigned Ab = sa32(As + (kt & 1) * GA_HALF);
        const unsigned Bb = sa32(Bs + (kt & 1) * GA_HALF);
#pragma unroll
        for (int ks = 0; ks < 4; ks++) {
            unsigned a[4][4], b[4][2];
#pragma unroll
            for (int mt = 0; mt < 4; mt++)
                ldsm_x4(a[mt][0], a[mt][1], a[mt][2], a[mt][3],
                        Ab + aoff + mt * 2304 + 32 * ks);
#pragma unroll
            for (int nt = 0; nt < 4; nt++)
                ldsm_x2(b[nt][0], b[nt][1], Bb + boff + nt * 1152 + 32 * ks);
#pragma unroll
            for (int mt = 0; mt < 4; mt++)
#pragma unroll
                for (int nt = 0; nt < 4; nt++)
                    mma16(acc[mt][nt], a[mt], b[nt]);
        }
        __syncthreads();
    }

    // epilogue
#pragma unroll
    for (int mt = 0; mt < 4; mt++) {
        const int r0 = m0 + wm + mt * 16 + g;
#pragma unroll
        for (int nt = 0; nt < 4; nt++) {
            const int c0 = n0 + wn + nt * 8 + 2 * t;
#pragma unroll
            for (int e = 0; e < 4; e++) {
                const int r = r0 + (e >> 1) * 8;
                const int c = c0 + (e & 1);
                const float val = acc[mt][nt][e] + bias[c];
                if (is_outproj) {
                    g_pre[(size_t)r * DD + c] = val + resid[(size_t)r * DD + c];
                } else {
                    const int b = r >> 9, l = r & 511;
                    const int h = c >> 6, d = c & 63;
                    const int bh = (b << 4) + h;
                    if (z == 0)
                        g_qh[(size_t)(bh * LLEN + l) * 64 + d] = __float2half(val * 0.125f);
                    else if (z == 1)
                        g_kh[(size_t)(bh * LLEN + l) * 64 + d] = __float2half(val);
                    else
                        g_vt[(size_t)(bh * 64 + d) * LLEN + l] = __float2half(val);
                }
            }
        }
    }
}

// ---------------- attention: 64-key sub-blocks, 2 CTAs/SM ---------------------
// K tile [64 key][72h]; V^T tile [64 dv][72h]; double buffered.
#define AKT_HALF (64 * 72)               // 4608 halves per buffer
#define ATTN_SMEM_BYTES (4 * AKT_HALF * 2)   // 36864

__global__ __launch_bounds__(256, 2)
void attn_kernel(const float* __restrict__ bias, const float* __restrict__ gbias)
{
    extern __shared__ __half smh[];
    __half* Ksm = smh;                   // [2][AKT_HALF]
    __half* Vsm = smh + 2 * AKT_HALF;    // [2][AKT_HALF]

    const int tid = threadIdx.x;
    const int w = tid >> 5, lane = tid & 31;
    const int g = lane >> 2, t = lane & 3;
    const int bh = blockIdx.y;           // b*16 + h
    const int q0 = blockIdx.x * 128;

    const __half* kbase = g_kh + (size_t)bh * LLEN * 64;
    const __half* vtb   = g_vt + (size_t)bh * 64 * LLEN;

    const int rowg = q0 + w * 16 + g;
    const float* bp0 = bias  + (size_t)(bh * LLEN + rowg) * LLEN;
    const float* bp1 = bp0 + 8 * LLEN;
    const float* gp0 = gbias + (size_t)(bh * LLEN + rowg) * LLEN;
    const float* gp1 = gp0 + 8 * LLEN;

    auto stage = [&](int kb, int buf) {
        const int k0 = kb * 64;
        const unsigned kbm = sa32(Ksm + buf * AKT_HALF);
        const unsigned vbm = sa32(Vsm + buf * AKT_HALF);
#pragma unroll
        for (int i = 0; i < 2; i++) {
            const int id = i * 256 + tid;
            const int row = id >> 3, c = id & 7;
            cpa16(kbm + row * 144 + c * 16,
                  kbase + (size_t)(k0 + row) * 64 + c * 8);
            cpa16(vbm + row * 144 + c * 16,
                  vtb + (size_t)row * LLEN + k0 + c * 8);
        }
    };

    // Q A-fragments, reused across all key blocks
    unsigned aq[4][4];
    {
        const __half* qr0 = g_qh + (size_t)(bh * LLEN + rowg) * 64;
        const __half* qr1 = qr0 + 8 * 64;
#pragma unroll
        for (int ks = 0; ks < 4; ks++) {
            aq[ks][0] = *(const unsigned*)&qr0[16 * ks + 2 * t];
            aq[ks][1] = *(const unsigned*)&qr1[16 * ks + 2 * t];
            aq[ks][2] = *(const unsigned*)&qr0[16 * ks + 2 * t + 8];
            aq[ks][3] = *(const unsigned*)&qr1[16 * ks + 2 * t + 8];
        }
    }

    float m0r = -1e30f, m1r = -1e30f, l0 = 0.f, l1 = 0.f;
    float o[8][4];
#pragma unroll
    for (int nt = 0; nt < 8; nt++)
#pragma unroll
        for (int e = 0; e < 4; e++) o[nt][e] = 0.f;

    stage(0, 0); CP_COMMIT();

    for (int kb = 0; kb < 8; kb++) {
        const int k0 = kb * 64;
        if (kb < 7) { stage(kb + 1, (kb + 1) & 1); CP_COMMIT(); CP_WAIT(1); }
        else        { CP_WAIT(0); }
        __syncthreads();

        const unsigned* Ku = (const unsigned*)(Ksm + (kb & 1) * AKT_HALF);
        const unsigned* Vu = (const unsigned*)(Vsm + (kb & 1) * AKT_HALF);

        // ---- S = Q K^T : 8 c-fragments (16 q x 64 keys) ----
        float s[8][4];
#pragma unroll
        for (int nt = 0; nt < 8; nt++)
#pragma unroll
            for (int e = 0; e < 4; e++) s[nt][e] = 0.f;

#pragma unroll
        for (int ks = 0; ks < 4; ks++) {
#pragma unroll
            for (int nt = 0; nt < 8; nt++) {
                unsigned b[2];
                b[0] = Ku[(nt * 8 + g) * 36 + 8 * ks + t];
                b[1] = Ku[(nt * 8 + g) * 36 + 8 * ks + t + 4];
                mma16(s[nt], aq[ks], b);
            }
        }

        // ---- biases + row maxima ----
        float mx0 = -1e30f, mx1 = -1e30f;
#pragma unroll 4
        for (int nt = 0; nt < 8; nt++) {
            const int c = k0 + nt * 8 + 2 * t;
            float2 b0 = *(const float2*)&bp0[c];
            float2 gb0 = *(const float2*)&gp0[c];
            float2 b1 = *(const float2*)&bp1[c];
            float2 gb1 = *(const float2*)&gp1[c];
            s[nt][0] += b0.x + gb0.x; s[nt][1] += b0.y + gb0.y;
            s[nt][2] += b1.x + gb1.x; s[nt][3] += b1.y + gb1.y;
            mx0 = fmaxf(mx0, fmaxf(s[nt][0], s[nt][1]));
            mx1 = fmaxf(mx1, fmaxf(s[nt][2], s[nt][3]));
        }
        mx0 = fmaxf(mx0, __shfl_xor_sync(0xffffffffu, mx0, 1));
        mx0 = fmaxf(mx0, __shfl_xor_sync(0xffffffffu, mx0, 2));
        mx1 = fmaxf(mx1, __shfl_xor_sync(0xffffffffu, mx1, 1));
        mx1 = fmaxf(mx1, __shfl_xor_sync(0xffffffffu, mx1, 2));

        const float mn0 = fmaxf(m0r, mx0), mn1 = fmaxf(m1r, mx1);
        const float fac0 = __expf(m0r - mn0), fac1 = __expf(m1r - mn1);
        m0r = mn0; m1r = mn1;

        float ls0 = 0.f, ls1 = 0.f;
#pragma unroll
        for (int nt = 0; nt < 8; nt++) {
            s[nt][0] = __expf(s[nt][0] - mn0);
            s[nt][1] = __expf(s[nt][1] - mn0);
            s[nt][2] = __expf(s[nt][2] - mn1);
            s[nt][3] = __expf(s[nt][3] - mn1);
            ls0 += s[nt][0] + s[nt][1];
            ls1 += s[nt][2] + s[nt][3];
        }
        l0 = l0 * fac0 + ls0;
        l1 = l1 * fac1 + ls1;
#pragma unroll
        for (int nt = 0; nt < 8; nt++) {
            o[nt][0] *= fac0; o[nt][1] *= fac0;
            o[nt][2] *= fac1; o[nt][3] *= fac1;
        }

        // ---- O += P V (P converted in registers) ----
#pragma unroll
        for (int ks = 0; ks < 4; ks++) {
            unsigned ap[4];
            ap[0] = pack_h2(s[2 * ks][0], s[2 * ks][1]);
            ap[1] = pack_h2(s[2 * ks][2], s[2 * ks][3]);
            ap[2] = pack_h2(s[2 * ks + 1][0], s[2 * ks + 1][1]);
            ap[3] = pack_h2(s[2 * ks + 1][2], s[2 * ks + 1][3]);
#pragma unroll
            for (int nt = 0; nt < 8; nt++) {
                unsigned bv[2];
                bv[0] = Vu[(nt * 8 + g) * 36 + 8 * ks + t];
                bv[1] = Vu[(nt * 8 + g) * 36 + 8 * ks + t + 4];
                mma16(o[nt], ap, bv);
            }
        }
        __syncthreads();
    }

    // ---- finalize ----
    l0 += __shfl_xor_sync(0xffffffffu, l0, 1);
    l0 += __shfl_xor_sync(0xffffffffu, l0, 2);
    l1 += __shfl_xor_sync(0xffffffffu, l1, 1);
    l1 += __shfl_xor_sync(0xffffffffu, l1, 2);
    const float inv0 = 1.0f / l0, inv1 = 1.0f / l1;

    const int b = bh >> 4, h = bh & 15;
    __half* c0 = &g_ctx[(size_t)(b * LLEN + rowg) * DD + h * 64];
    __half* c1 = c0 + 8 * (size_t)DD;
#pragma unroll
    for (int nt = 0; nt < 8; nt++) {
        *(__half2*)&c0[nt * 8 + 2 * t] = __floats2half2_rn(o[nt][0] * inv0, o[nt][1] * inv0);
        *(__half2*)&c1[nt * 8 + 2 * t] = __floats2half2_rn(o[nt][2] * inv1, o[nt][3] * inv1);
    }
}

// ---------------- LayerNorm: grid 2048, 256 threads ----------------
__global__ __launch_bounds__(256)
void ln_kernel(const float* __restrict__ gamma, const float* __restrict__ beta,
               float* __restrict__ out)
{
    __shared__ float red[8];
    const int row = blockIdx.x, tid = threadIdx.x;
    const float4 xv = *(const float4*)&g_pre[(size_t)row * DD + tid * 4];

    float sv = xv.x + xv.y + xv.z + xv.w;
#pragma unroll
    for (int off = 16; off > 0; off >>= 1) sv += __shfl_xor_sync(0xffffffffu, sv, off);
    if ((tid & 31) == 0) red[tid >> 5] = sv;
    __syncthreads();
    float tot = 0.f;
#pragma unroll
    for (int w = 0; w < 8; w++) tot += red[w];
    const float mean = tot * (1.0f / 1024.0f);

    const float dx = xv.x - mean, dy = xv.y - mean, dz = xv.z - mean, dw = xv.w - mean;
    float ss = dx * dx + dy * dy + dz * dz + dw * dw;
    __syncthreads();
#pragma unroll
    for (int off = 16; off > 0; off >>= 1) ss += __shfl_xor_sync(0xffffffffu, ss, off);
    if ((tid & 31) == 0) red[tid >> 5] = ss;
    __syncthreads();
    float tot2 = 0.f;
#pragma unroll
    for (int w = 0; w < 8; w++) tot2 += red[w];
    const float rstd = rsqrtf(tot2 * (1.0f / 1024.0f) + 1e-6f);

    const float4 gv = *(const float4*)&gamma[tid * 4];
    const float4 bv = *(const float4*)&beta[tid * 4];
    float4 ov;
    ov.x = dx * rstd * gv.x + bv.x;
    ov.y = dy * rstd * gv.y + bv.y;
    ov.z = dz * rstd * gv.z + bv.z;
    ov.w = dw * rstd * gv.w + bv.w;
    *(float4*)&out[(size_t)row * DD + tid * 4] = ov;
}

// ---------------- launch ----------------
extern "C" void kernel_launch(void* const* d_in, const int* in_sizes, int n_in,
                              void* d_out, int out_size)
{
    const float* q     = (const float*)d_in[0];
    const float* k     = (const float*)d_in[1];
    const float* v     = (const float*)d_in[2];
    const float* bias  = (const float*)d_in[3];
    const float* gbias = (const float*)d_in[4];
    const float* wq    = (const float*)d_in[5];
    const float* bq    = (const float*)d_in[6];
    const float* wk    = (const float*)d_in[7];
    const float* bk    = (const float*)d_in[8];
    const float* wv    = (const float*)d_in[9];
    const float* bv    = (const float*)d_in[10];
    const float* wo    = (const float*)d_in[11];
    const float* bo    = (const float*)d_in[12];
    const float* ln_g  = (const float*)d_in[13];
    const float* ln_b  = (const float*)d_in[14];
    float* out = (float*)d_out;

    cudaFuncSetAttribute(gemm16,
                         cudaFuncAttributeMaxDynamicSharedMemorySize, GEMM_SMEM_BYTES);
    cudaFuncSetAttribute(attn_kernel,
                         cudaFuncAttributeMaxDynamicSharedMemorySize, ATTN_SMEM_BYTES);

    prep_kernel<<<dim3(32, 32, 7), 256>>>(q, k, v, wq, wk, wv, wo);
    gemm16<<<dim3(8, 16, 3), 256, GEMM_SMEM_BYTES>>>(0, nullptr, bq, bk, bv);
    attn_kernel<<<dim3(4, 64), 256, ATTN_SMEM_BYTES>>>(bias, gbias);
    gemm16<<<dim3(8, 16, 1), 256, GEMM_SMEM_BYTES>>>(1, q, bo, nullptr, nullptr);
    ln_kernel<<<2048, 256>>>(ln_g, ln_b, out);
}